// round 14
// baseline (speedup 1.0000x reference)
#include <cuda_runtime.h>
#include <cuda_fp16.h>
#include <math.h>
#include <stdint.h>

// ---------------------------------------------------------------------------
// 3-layer GCN (N=100000, E=1600000, C: 128->128->128->64) + edge MLP.
// GEMMs: fp16 mma.sync.m16n8k16; weights pre-transposed fp16; GEMM0 converts
// fp32 A inline; GEMM1/2 prescale rows by dinv. Aggregation: padded 4-aligned
// CSR (sentinel index N -> zero row), uint4 index loads, 16B/lane row gathers.
// The C=64 sentinel row (g_H + N*64) overlaps layer-1 data and must be
// re-zeroed after hgemm<64> (R13 bug). Layer2 folded with mlp_w1.
// edge_index is int32 (JAX x64 disabled).
// ---------------------------------------------------------------------------

#define MAXN 100000
#define MAXE 2000000
#define SCAN_B 1024
#define MAXBLK 128

__device__ __half g_H[(size_t)(MAXN + 1) * 128];   // fp16 gather table (+zero row)
__device__ __half g_C16[(size_t)MAXN * 128];       // fp16 activations (h / P)
__device__ float  g_dinv[MAXN + 1];                // dinv[N] = 0 (pad sentinel)
__device__ int    g_deg[MAXN];
__device__ int    g_rowptr[MAXN + 1];
__device__ int    g_fill[MAXN];
__device__ int    g_csr[MAXE];
__device__ int    g_bsum[MAXBLK];
__device__ int    g_ptot;
__device__ __half g_W0t[128 * 128];
__device__ __half g_W1t[128 * 128];
__device__ __half g_W2t[64 * 128];
__device__ float  g_b2p[64];

// ------------------------------ degree / CSR --------------------------------
__global__ void deg_zero_kernel(int N) {
    int i = blockIdx.x * blockDim.x + threadIdx.x;
    if (i < N) { g_deg[i] = 0; g_fill[i] = 0; }
    if (i < 128) g_H[(size_t)N * 128 + i] = __float2half_rn(0.f);  // C=128 zero row
}

// Zero the sentinel row for a C-wide table: h[N*C .. N*C+C).
__global__ void zero_row_kernel(__half* __restrict__ h, int N, int C) {
    int i = threadIdx.x;
    if (i < C) h[(size_t)N * C + i] = __float2half_rn(0.f);
}

__global__ void deg_count_kernel(const int* __restrict__ dst, int E) {
    int i = blockIdx.x * blockDim.x + threadIdx.x;
    if (i < E) atomicAdd(&g_deg[dst[i]], 1);
}

// Pre-fill csr with sentinel N so pad slots gather the zero row.
__global__ void csr_prefill_kernel(int total, int N) {
    int i = blockIdx.x * blockDim.x + threadIdx.x;
    if (i < total) g_csr[i] = N;
}

// Scan PADDED degrees ((deg+3)&~3) -> 4-aligned row starts.
__global__ void partial_scan_kernel(int N) {
    __shared__ int wsum[32];
    __shared__ int wpre[32];
    const int lane = threadIdx.x & 31;
    const int wid  = threadIdx.x >> 5;
    const int i = blockIdx.x * SCAN_B + threadIdx.x;
    const int v = (i < N) ? g_deg[i] : 0;
    if (i < N) g_dinv[i] = rsqrtf((float)(v + 1));  // +1 self loop
    const int pv = (i < N) ? ((v + 3) & ~3) : 0;

    int inc = pv;
#pragma unroll
    for (int o = 1; o < 32; o <<= 1) {
        int t = __shfl_up_sync(0xffffffffu, inc, o);
        if (lane >= o) inc += t;
    }
    if (lane == 31) wsum[wid] = inc;
    __syncthreads();
    if (wid == 0) {
        int s = wsum[lane];
        int sinc = s;
#pragma unroll
        for (int o = 1; o < 32; o <<= 1) {
            int t = __shfl_up_sync(0xffffffffu, sinc, o);
            if (lane >= o) sinc += t;
        }
        wpre[lane] = sinc - s;
        if (lane == 31) wsum[0] = sinc;
    }
    __syncthreads();
    if (i < N) g_rowptr[i] = wpre[wid] + inc - pv;
    if (threadIdx.x == 0) g_bsum[blockIdx.x] = wsum[0];
}

__global__ void bsum_scan_kernel(int nb) {
    __shared__ int ws[4];
    const int lane = threadIdx.x & 31;
    const int wid  = threadIdx.x >> 5;
    const int v = (threadIdx.x < nb) ? g_bsum[threadIdx.x] : 0;
    int inc = v;
#pragma unroll
    for (int o = 1; o < 32; o <<= 1) {
        int t = __shfl_up_sync(0xffffffffu, inc, o);
        if (lane >= o) inc += t;
    }
    if (lane == 31) ws[wid] = inc;
    __syncthreads();
    int pre = 0;
#pragma unroll
    for (int w = 0; w < 4; w++) if (w < wid) pre += ws[w];
    if (threadIdx.x == nb - 1) g_ptot = pre + inc;          // padded total
    if (threadIdx.x < nb) g_bsum[threadIdx.x] = pre + inc - v;
}

__global__ void add_offsets_kernel(int N) {
    int i = blockIdx.x * blockDim.x + threadIdx.x;
    if (i < N) g_rowptr[i] += g_bsum[i >> 10];
    if (i == N) { g_rowptr[N] = g_ptot; g_dinv[N] = 0.f; }
}

__global__ void fill_kernel(const int* __restrict__ src, const int* __restrict__ dst, int E) {
    int e = blockIdx.x * blockDim.x + threadIdx.x;
    if (e < E) {
        const int d = dst[e];
        const int pos = g_rowptr[d] + atomicAdd(&g_fill[d], 1);
        g_csr[pos] = src[e];
    }
}

// ---------------------------- weight preparation -----------------------------
__global__ void prep_wt_kernel(const float* __restrict__ W, __half* __restrict__ Wt,
                               int K, int Ncols) {
    const int idx = blockIdx.x * blockDim.x + threadIdx.x;
    if (idx < K * Ncols) {
        const int k = idx / Ncols;
        const int n = idx % Ncols;
        Wt[n * K + k] = __float2half_rn(W[idx]);
    }
}

__global__ void fold_w2t_kernel(const float* __restrict__ W2, const float* __restrict__ mw1) {
    const int j = blockIdx.x;     // 0..63
    const int i = threadIdx.x;    // 0..127
    float s = 0.f;
#pragma unroll 8
    for (int k = 0; k < 64; k++)
        s = fmaf(W2[i * 64 + k], mw1[k * 64 + j], s);
    g_W2t[j * 128 + i] = __float2half_rn(s);
}

__global__ void fold_b2_kernel(const float* __restrict__ b2, const float* __restrict__ mw1) {
    const int j = threadIdx.x;
    float s = 0.f;
#pragma unroll 8
    for (int k = 0; k < 64; k++)
        s = fmaf(b2[k], mw1[k * 64 + j], s);
    g_b2p[j] = s;
}

// ------------------------------ fp16 GEMM -----------------------------------
__device__ __forceinline__ void mma_f16(float* c, uint32_t a0, uint32_t a1,
                                        uint32_t a2, uint32_t a3,
                                        uint32_t b0, uint32_t b1) {
    asm volatile(
        "mma.sync.aligned.m16n8k16.row.col.f32.f16.f16.f32 "
        "{%0,%1,%2,%3}, {%4,%5,%6,%7}, {%8,%9}, {%0,%1,%2,%3};"
        : "+f"(c[0]), "+f"(c[1]), "+f"(c[2]), "+f"(c[3])
        : "r"(a0), "r"(a1), "r"(a2), "r"(a3), "r"(b0), "r"(b1));
}

template <int BN, typename AT, bool SCALE>
__global__ void __launch_bounds__(256)
hgemm_kernel(const AT* __restrict__ A, const __half* __restrict__ Wt,
             __half* __restrict__ out, int M, int K) {
    constexpr int BM = 128, BK = 32;
    constexpr int SA = BK + 8;
    constexpr int SB = BK + 8;
    constexpr int WTN = BN / 4;
    constexpr int MB = 4;
    constexpr int NB = WTN / 8;

    __shared__ __half As[BM * SA];
    __shared__ __half Bs[BN * SB];

    const int tid  = threadIdx.x;
    const int lane = tid & 31;
    const int wid  = tid >> 5;
    const int wr   = wid >> 2;
    const int wc   = wid & 3;
    const int rowBlock = blockIdx.x * BM;

    float acc[MB][NB][4];
#pragma unroll
    for (int i = 0; i < MB; i++)
#pragma unroll
        for (int j = 0; j < NB; j++)
#pragma unroll
            for (int q = 0; q < 4; q++) acc[i][j][q] = 0.0f;

    const int lq = lane >> 2;
    const int lr = lane & 3;

    for (int kb = 0; kb < K; kb += BK) {
#pragma unroll
        for (int i = 0; i < 2; i++) {
            const int f  = tid + i * 256;
            const int r  = f >> 2;
            const int c0 = (f & 3) * 8;
            const int gr = rowBlock + r;
            uint4 v = make_uint4(0, 0, 0, 0);
            if (gr < M) {
                if constexpr (sizeof(AT) == 2) {
                    v = *reinterpret_cast<const uint4*>(
                        reinterpret_cast<const __half*>(A) + (size_t)gr * K + kb + c0);
                } else {
                    const float* ap = reinterpret_cast<const float*>(A) + (size_t)gr * K + kb + c0;
                    const float4 u0 = *reinterpret_cast<const float4*>(ap);
                    const float4 u1 = *reinterpret_cast<const float4*>(ap + 4);
                    *reinterpret_cast<__half2*>(&v.x) = __float22half2_rn(make_float2(u0.x, u0.y));
                    *reinterpret_cast<__half2*>(&v.y) = __float22half2_rn(make_float2(u0.z, u0.w));
                    *reinterpret_cast<__half2*>(&v.z) = __float22half2_rn(make_float2(u1.x, u1.y));
                    *reinterpret_cast<__half2*>(&v.w) = __float22half2_rn(make_float2(u1.z, u1.w));
                }
            }
            *reinterpret_cast<uint4*>(&As[r * SA + c0]) = v;
        }
#pragma unroll
        for (int i = 0; i < BN / 64; i++) {
            const int f  = tid + i * 256;
            const int n  = f >> 2;
            const int c0 = (f & 3) * 8;
            *reinterpret_cast<uint4*>(&Bs[n * SB + c0]) =
                *reinterpret_cast<const uint4*>(Wt + (size_t)n * K + kb + c0);
        }
        __syncthreads();

#pragma unroll
        for (int k16 = 0; k16 < BK / 16; k16++) {
            const int cb = k16 * 16 + 2 * lr;
            uint32_t af[MB][4];
#pragma unroll
            for (int mb = 0; mb < MB; mb++) {
                const int r = wr * 64 + mb * 16 + lq;
                af[mb][0] = *reinterpret_cast<const uint32_t*>(&As[r * SA + cb]);
                af[mb][1] = *reinterpret_cast<const uint32_t*>(&As[(r + 8) * SA + cb]);
                af[mb][2] = *reinterpret_cast<const uint32_t*>(&As[r * SA + cb + 8]);
                af[mb][3] = *reinterpret_cast<const uint32_t*>(&As[(r + 8) * SA + cb + 8]);
            }
            uint32_t bf[NB][2];
#pragma unroll
            for (int nb = 0; nb < NB; nb++) {
                const int n = wc * WTN + nb * 8 + lq;
                bf[nb][0] = *reinterpret_cast<const uint32_t*>(&Bs[n * SB + cb]);
                bf[nb][1] = *reinterpret_cast<const uint32_t*>(&Bs[n * SB + cb + 8]);
            }
#pragma unroll
            for (int mb = 0; mb < MB; mb++)
#pragma unroll
                for (int nb = 0; nb < NB; nb++)
                    mma_f16(acc[mb][nb], af[mb][0], af[mb][1], af[mb][2], af[mb][3],
                            bf[nb][0], bf[nb][1]);
        }
        __syncthreads();
    }

#pragma unroll
    for (int mb = 0; mb < MB; mb++) {
        const int r0 = rowBlock + wr * 64 + mb * 16 + lq;
        const int r1 = r0 + 8;
        float s0 = 1.f, s1 = 1.f;
        if (SCALE) {
            if (r0 < M) s0 = g_dinv[r0];
            if (r1 < M) s1 = g_dinv[r1];
        }
#pragma unroll
        for (int nb = 0; nb < NB; nb++) {
            const int c = wc * WTN + nb * 8 + lr * 2;
            if (r0 < M)
                *reinterpret_cast<__half2*>(out + (size_t)r0 * BN + c) =
                    __float22half2_rn(make_float2(acc[mb][nb][0] * s0, acc[mb][nb][1] * s0));
            if (r1 < M)
                *reinterpret_cast<__half2*>(out + (size_t)r1 * BN + c) =
                    __float22half2_rn(make_float2(acc[mb][nb][2] * s1, acc[mb][nb][3] * s1));
        }
    }
}

// ----------------------------- aggregation ----------------------------------
struct F8 { float v[8]; };

__device__ __forceinline__ F8 h8_to_f8(uint4 r) {
    F8 o;
    const float2 f0 = __half22float2(*reinterpret_cast<const __half2*>(&r.x));
    const float2 f1 = __half22float2(*reinterpret_cast<const __half2*>(&r.y));
    const float2 f2 = __half22float2(*reinterpret_cast<const __half2*>(&r.z));
    const float2 f3 = __half22float2(*reinterpret_cast<const __half2*>(&r.w));
    o.v[0] = f0.x; o.v[1] = f0.y; o.v[2] = f1.x; o.v[3] = f1.y;
    o.v[4] = f2.x; o.v[5] = f2.y; o.v[6] = f3.x; o.v[7] = f3.y;
    return o;
}

// Padded CSR: segment lengths multiples of 4, pads -> zero row N.
template <int C, int RELU, bool PRESCALED>
__global__ void agg_kernel(const __half* __restrict__ h, const float* __restrict__ b,
                           __half* __restrict__ out, int N) {
    constexpr int G = C / 8;
    const long long gt = (long long)blockIdx.x * blockDim.x + threadIdx.x;
    const int node = (int)(gt / G);
    const int lane = (int)(gt % G);
    if (node >= N) return;

    const int beg = g_rowptr[node];
    const int end = g_rowptr[node + 1];
    const size_t col = (size_t)lane * 8;
    const float di = g_dinv[node];

    const F8 self = h8_to_f8(*reinterpret_cast<const uint4*>(h + (size_t)node * C + col));
    float acc[8];
#pragma unroll
    for (int q = 0; q < 8; q++) acc[q] = PRESCALED ? self.v[q] : self.v[q] * di;

    for (int k = beg; k < end; k += 4) {
        const uint4 s4 = __ldg(reinterpret_cast<const uint4*>(&g_csr[k]));
        const int s0 = (int)s4.x, s1 = (int)s4.y, s2 = (int)s4.z, s3 = (int)s4.w;
        const F8 v0 = h8_to_f8(__ldg(reinterpret_cast<const uint4*>(h + (size_t)s0 * C + col)));
        const F8 v1 = h8_to_f8(__ldg(reinterpret_cast<const uint4*>(h + (size_t)s1 * C + col)));
        const F8 v2 = h8_to_f8(__ldg(reinterpret_cast<const uint4*>(h + (size_t)s2 * C + col)));
        const F8 v3 = h8_to_f8(__ldg(reinterpret_cast<const uint4*>(h + (size_t)s3 * C + col)));
        if (PRESCALED) {
#pragma unroll
            for (int q = 0; q < 8; q++)
                acc[q] += (v0.v[q] + v1.v[q]) + (v2.v[q] + v3.v[q]);
        } else {
            const float d0 = __ldg(&g_dinv[s0]);
            const float d1 = __ldg(&g_dinv[s1]);
            const float d2 = __ldg(&g_dinv[s2]);
            const float d3 = __ldg(&g_dinv[s3]);
#pragma unroll
            for (int q = 0; q < 8; q++) {
                acc[q] = fmaf(v0.v[q], d0, acc[q]);
                acc[q] = fmaf(v1.v[q], d1, acc[q]);
                acc[q] = fmaf(v2.v[q], d2, acc[q]);
                acc[q] = fmaf(v3.v[q], d3, acc[q]);
            }
        }
    }

    const float4 b0 = __ldg(reinterpret_cast<const float4*>(b + col));
    const float4 b1 = __ldg(reinterpret_cast<const float4*>(b + col + 4));
    const float bb[8] = {b0.x, b0.y, b0.z, b0.w, b1.x, b1.y, b1.z, b1.w};
    float r[8];
#pragma unroll
    for (int q = 0; q < 8; q++) {
        r[q] = fmaf(acc[q], di, bb[q]);
        if (RELU) r[q] = fmaxf(r[q], 0.f);
    }
    uint4 o;
    *reinterpret_cast<__half2*>(&o.x) = __float22half2_rn(make_float2(r[0], r[1]));
    *reinterpret_cast<__half2*>(&o.y) = __float22half2_rn(make_float2(r[2], r[3]));
    *reinterpret_cast<__half2*>(&o.z) = __float22half2_rn(make_float2(r[4], r[5]));
    *reinterpret_cast<__half2*>(&o.w) = __float22half2_rn(make_float2(r[6], r[7]));
    *reinterpret_cast<uint4*>(out + (size_t)node * C + col) = o;
}

// -------------------------------- edge MLP ----------------------------------
// 8 lanes per edge (4 edges/warp); each lane loads 16B (8 halves) of src+dst P.
__global__ void edge_mlp_kernel(const int* __restrict__ src,
                                const int* __restrict__ dst,
                                const __half* __restrict__ P,     // [N,64] fp16
                                const float* __restrict__ b1,     // [64]
                                const float* __restrict__ w2,     // [64,2]
                                const float* __restrict__ b2,     // [2]
                                float* __restrict__ out, int E) {
    const long long gt = (long long)blockIdx.x * blockDim.x + threadIdx.x;
    const int edge = (int)(gt >> 3);
    const int lane = (int)(gt & 7);
    if (edge >= E) return;
    const int s = src[edge];
    const int d = dst[edge];
    const F8 ps = h8_to_f8(__ldg(reinterpret_cast<const uint4*>(P + (size_t)s * 64 + lane * 8)));
    const F8 pd = h8_to_f8(__ldg(reinterpret_cast<const uint4*>(P + (size_t)d * 64 + lane * 8)));
    const float4 bA = *reinterpret_cast<const float4*>(b1 + lane * 8);
    const float4 bB = *reinterpret_cast<const float4*>(b1 + lane * 8 + 4);
    const float bb[8] = {bA.x, bA.y, bA.z, bA.w, bB.x, bB.y, bB.z, bB.w};
    float q[8];
#pragma unroll
    for (int j = 0; j < 8; j++)
        q[j] = fmaxf(0.f, fmaf(ps.v[j] + pd.v[j], 0.5f, bb[j]));
    const float4 w0 = *reinterpret_cast<const float4*>(w2 + lane * 16);
    const float4 w1 = *reinterpret_cast<const float4*>(w2 + lane * 16 + 4);
    const float4 w2v = *reinterpret_cast<const float4*>(w2 + lane * 16 + 8);
    const float4 w3 = *reinterpret_cast<const float4*>(w2 + lane * 16 + 12);
    const float ww[16] = {w0.x, w0.y, w0.z, w0.w, w1.x, w1.y, w1.z, w1.w,
                          w2v.x, w2v.y, w2v.z, w2v.w, w3.x, w3.y, w3.z, w3.w};
    float y0 = 0.f, y1 = 0.f;
#pragma unroll
    for (int j = 0; j < 8; j++) {
        y0 = fmaf(q[j], ww[2 * j], y0);
        y1 = fmaf(q[j], ww[2 * j + 1], y1);
    }
#pragma unroll
    for (int o = 4; o > 0; o >>= 1) {
        y0 += __shfl_xor_sync(0xffffffffu, y0, o, 8);
        y1 += __shfl_xor_sync(0xffffffffu, y1, o, 8);
    }
    if (lane == 0) {
        float2 r;
        r.x = y0 + b2[0];
        r.y = y1 + b2[1];
        *reinterpret_cast<float2*>(out + (size_t)edge * 2) = r;
    }
}

// ---------------------------------------------------------------------------
extern "C" void kernel_launch(void* const* d_in, const int* in_sizes, int n_in,
                              void* d_out, int out_size) {
    const float* x   = (const float*)d_in[0];
    const int*   ei  = (const int*)d_in[1];   // int32
    const float* W0  = (const float*)d_in[2];
    const float* b0  = (const float*)d_in[3];
    const float* W1  = (const float*)d_in[4];
    const float* b1  = (const float*)d_in[5];
    const float* W2  = (const float*)d_in[6];
    const float* b2  = (const float*)d_in[7];
    const float* mw1 = (const float*)d_in[8];
    const float* mb1 = (const float*)d_in[9];
    const float* mw2 = (const float*)d_in[10];
    const float* mb2 = (const float*)d_in[11];
    float* out = (float*)d_out;

    const int N = in_sizes[0] / 128;
    const int E = in_sizes[1] / 2;
    const int* src = ei;
    const int* dst = ei + E;

    __half *pH, *pC16, *pW0t, *pW1t, *pW2t;
    float  *pb2p;
    cudaGetSymbolAddress((void**)&pH,   g_H);
    cudaGetSymbolAddress((void**)&pC16, g_C16);
    cudaGetSymbolAddress((void**)&pW0t, g_W0t);
    cudaGetSymbolAddress((void**)&pW1t, g_W1t);
    cudaGetSymbolAddress((void**)&pW2t, g_W2t);
    cudaGetSymbolAddress((void**)&pb2p, g_b2p);

    const int T = 256;
    const int nScanBlocks = (N + SCAN_B - 1) / SCAN_B;
    const int padTotal = E + 3 * N + 4;

    static cudaStream_t s_side = (cudaStream_t)(-1);
    static cudaEvent_t  ev_fork = nullptr, ev_join = nullptr;
    if (s_side == (cudaStream_t)(-1)) {
        cudaStream_t tmp;
        if (cudaStreamCreateWithFlags(&tmp, cudaStreamNonBlocking) == cudaSuccess &&
            cudaEventCreateWithFlags(&ev_fork, cudaEventDisableTiming) == cudaSuccess &&
            cudaEventCreateWithFlags(&ev_join, cudaEventDisableTiming) == cudaSuccess) {
            s_side = tmp;
        } else {
            s_side = nullptr;
        }
    }
    const bool overlap = (s_side != nullptr);
    cudaStream_t sc = overlap ? s_side : (cudaStream_t)0;

    if (overlap) {
        cudaEventRecord(ev_fork, 0);
        cudaStreamWaitEvent(s_side, ev_fork, 0);
    }

    const int gM = (N + 127) / 128;
    const int agg128 = (int)(((long long)N * 16 + T - 1) / T);
    const int agg64  = (int)(((long long)N * 8 + T - 1) / T);

    // main: GEMM0 (fp32 A, converts inline) ; side: CSR + weight prep
    prep_wt_kernel<<<(128 * 128 + T - 1) / T, T>>>(W0, pW0t, 128, 128);
    deg_zero_kernel<<<(N + T - 1) / T, T, 0, sc>>>(N);
    deg_count_kernel<<<(E + T - 1) / T, T, 0, sc>>>(dst, E);
    csr_prefill_kernel<<<(padTotal + T - 1) / T, T, 0, sc>>>(padTotal, N);
    partial_scan_kernel<<<nScanBlocks, SCAN_B, 0, sc>>>(N);
    hgemm_kernel<128, float, false><<<gM, T>>>(x, pW0t, pH, N, 128);
    bsum_scan_kernel<<<1, 128, 0, sc>>>(nScanBlocks);
    add_offsets_kernel<<<(N + T) / T, T, 0, sc>>>(N);
    fill_kernel<<<(E + T - 1) / T, T, 0, sc>>>(src, dst, E);
    prep_wt_kernel<<<(128 * 128 + T - 1) / T, T, 0, sc>>>(W1, pW1t, 128, 128);
    fold_w2t_kernel<<<64, 128, 0, sc>>>(W2, mw1);
    fold_b2_kernel<<<1, 64, 0, sc>>>(b2, mw1);

    if (overlap) {
        cudaEventRecord(ev_join, s_side);
        cudaStreamWaitEvent(0, ev_join, 0);
    }

    // ---- GCN layer 0 agg (dinv gathered; pads: dinv[N]=0) ----
    agg_kernel<128, 1, false><<<agg128, T>>>(pH, b0, pC16, N);

    // ---- GCN layer 1 (prescaled -> pure-add agg; zero row N*128 intact) ----
    hgemm_kernel<128, __half, true><<<gM, T>>>(pC16, pW1t, pH, N, 128);
    agg_kernel<128, 1, true><<<agg128, T>>>(pH, b1, pC16, N);

    // ---- GCN layer 2 fused with mlp_w1 (prescaled, C=64) ----
    hgemm_kernel<64, __half, true><<<gM, T>>>(pC16, pW2t, pH, N, 128);
    zero_row_kernel<<<1, 64>>>(pH, N, 64);   // C=64 sentinel row overlaps old data
    agg_kernel<64, 0, true><<<agg64, T>>>(pH, pb2p, pC16, N);   // pC16 = P

    // ---- edge head ----
    edge_mlp_kernel<<<(int)(((long long)E * 8 + T - 1) / T), T>>>(src, dst, pC16, mb1, mw2, mb2, out, E);
}

// round 15
// speedup vs baseline: 1.0186x; 1.0186x over previous
#include <cuda_runtime.h>
#include <cuda_fp16.h>
#include <math.h>
#include <stdint.h>

// ---------------------------------------------------------------------------
// 3-layer GCN (N=100000, E=1600000, C: 128->128->128->64) + edge MLP.
// GEMMs: fp16 mma.sync.m16n8k16; weights pre-transposed fp16; GEMM0 converts
// fp32 A inline; GEMM1/2 prescale rows by dinv. Aggregation: padded 4-aligned
// CSR (sentinel index N -> zero row, filled per-node), uint4 index loads,
// 16B/lane row gathers. Layer2 folded with mlp_w1. Edge MLP: 16 lanes/edge.
// edge_index is int32 (JAX x64 disabled).
// ---------------------------------------------------------------------------

#define MAXN 100000
#define MAXE 2000000
#define SCAN_B 1024
#define MAXBLK 128

__device__ __half g_H[(size_t)(MAXN + 1) * 128];   // fp16 gather table (+zero row)
__device__ __half g_C16[(size_t)MAXN * 128];       // fp16 activations (h / P)
__device__ float  g_dinv[MAXN + 1];                // dinv[N] = 0 (pad sentinel)
__device__ int    g_deg[MAXN];
__device__ int    g_rowptr[MAXN + 1];
__device__ int    g_fill[MAXN];
__device__ int    g_csr[MAXE];
__device__ int    g_bsum[MAXBLK];
__device__ int    g_ptot;
__device__ __half g_W0t[128 * 128];
__device__ __half g_W1t[128 * 128];
__device__ __half g_W2t[64 * 128];
__device__ float  g_b2p[64];

// ------------------------------ degree / CSR --------------------------------
__global__ void deg_zero_kernel(int N) {
    int i = blockIdx.x * blockDim.x + threadIdx.x;
    if (i < N) { g_deg[i] = 0; g_fill[i] = 0; }
    if (i < 128) g_H[(size_t)N * 128 + i] = __float2half_rn(0.f);  // C=128 zero row
}

// Zero the sentinel row for a C-wide table: h[N*C .. N*C+C).
__global__ void zero_row_kernel(__half* __restrict__ h, int N, int C) {
    int i = threadIdx.x;
    if (i < C) h[(size_t)N * C + i] = __float2half_rn(0.f);
}

__global__ void deg_count_kernel(const int* __restrict__ dst, int E) {
    int i = blockIdx.x * blockDim.x + threadIdx.x;
    if (i < E) atomicAdd(&g_deg[dst[i]], 1);
}

// Scan PADDED degrees ((deg+3)&~3) -> 4-aligned row starts.
__global__ void partial_scan_kernel(int N) {
    __shared__ int wsum[32];
    __shared__ int wpre[32];
    const int lane = threadIdx.x & 31;
    const int wid  = threadIdx.x >> 5;
    const int i = blockIdx.x * SCAN_B + threadIdx.x;
    const int v = (i < N) ? g_deg[i] : 0;
    if (i < N) g_dinv[i] = rsqrtf((float)(v + 1));  // +1 self loop
    const int pv = (i < N) ? ((v + 3) & ~3) : 0;

    int inc = pv;
#pragma unroll
    for (int o = 1; o < 32; o <<= 1) {
        int t = __shfl_up_sync(0xffffffffu, inc, o);
        if (lane >= o) inc += t;
    }
    if (lane == 31) wsum[wid] = inc;
    __syncthreads();
    if (wid == 0) {
        int s = wsum[lane];
        int sinc = s;
#pragma unroll
        for (int o = 1; o < 32; o <<= 1) {
            int t = __shfl_up_sync(0xffffffffu, sinc, o);
            if (lane >= o) sinc += t;
        }
        wpre[lane] = sinc - s;
        if (lane == 31) wsum[0] = sinc;
    }
    __syncthreads();
    if (i < N) g_rowptr[i] = wpre[wid] + inc - pv;
    if (threadIdx.x == 0) g_bsum[blockIdx.x] = wsum[0];
}

__global__ void bsum_scan_kernel(int nb) {
    __shared__ int ws[4];
    const int lane = threadIdx.x & 31;
    const int wid  = threadIdx.x >> 5;
    const int v = (threadIdx.x < nb) ? g_bsum[threadIdx.x] : 0;
    int inc = v;
#pragma unroll
    for (int o = 1; o < 32; o <<= 1) {
        int t = __shfl_up_sync(0xffffffffu, inc, o);
        if (lane >= o) inc += t;
    }
    if (lane == 31) ws[wid] = inc;
    __syncthreads();
    int pre = 0;
#pragma unroll
    for (int w = 0; w < 4; w++) if (w < wid) pre += ws[w];
    if (threadIdx.x == nb - 1) g_ptot = pre + inc;          // padded total
    if (threadIdx.x < nb) g_bsum[threadIdx.x] = pre + inc - v;
}

__global__ void add_offsets_kernel(int N) {
    int i = blockIdx.x * blockDim.x + threadIdx.x;
    if (i < N) g_rowptr[i] += g_bsum[i >> 10];
    if (i == N) { g_rowptr[N] = g_ptot; g_dinv[N] = 0.f; }
}

// Write sentinel N into each node's pad slots [rowptr[i]+deg, rowptr[i]+pad).
// Disjoint from fill_kernel's range [rowptr[i], rowptr[i]+deg).
__global__ void pad_fill_kernel(int N) {
    int i = blockIdx.x * blockDim.x + threadIdx.x;
    if (i >= N) return;
    const int deg = g_deg[i];
    const int beg = g_rowptr[i] + deg;
    const int end = g_rowptr[i] + ((deg + 3) & ~3);
    for (int j = beg; j < end; j++) g_csr[j] = N;
}

__global__ void fill_kernel(const int* __restrict__ src, const int* __restrict__ dst, int E) {
    int e = blockIdx.x * blockDim.x + threadIdx.x;
    if (e < E) {
        const int d = dst[e];
        const int pos = g_rowptr[d] + atomicAdd(&g_fill[d], 1);
        g_csr[pos] = src[e];
    }
}

// ---------------------------- weight preparation -----------------------------
__global__ void prep_wt_kernel(const float* __restrict__ W, __half* __restrict__ Wt,
                               int K, int Ncols) {
    const int idx = blockIdx.x * blockDim.x + threadIdx.x;
    if (idx < K * Ncols) {
        const int k = idx / Ncols;
        const int n = idx % Ncols;
        Wt[n * K + k] = __float2half_rn(W[idx]);
    }
}

__global__ void fold_w2t_kernel(const float* __restrict__ W2, const float* __restrict__ mw1) {
    const int j = blockIdx.x;     // 0..63
    const int i = threadIdx.x;    // 0..127
    float s = 0.f;
#pragma unroll 8
    for (int k = 0; k < 64; k++)
        s = fmaf(W2[i * 64 + k], mw1[k * 64 + j], s);
    g_W2t[j * 128 + i] = __float2half_rn(s);
}

__global__ void fold_b2_kernel(const float* __restrict__ b2, const float* __restrict__ mw1) {
    const int j = threadIdx.x;
    float s = 0.f;
#pragma unroll 8
    for (int k = 0; k < 64; k++)
        s = fmaf(b2[k], mw1[k * 64 + j], s);
    g_b2p[j] = s;
}

// ------------------------------ fp16 GEMM -----------------------------------
__device__ __forceinline__ void mma_f16(float* c, uint32_t a0, uint32_t a1,
                                        uint32_t a2, uint32_t a3,
                                        uint32_t b0, uint32_t b1) {
    asm volatile(
        "mma.sync.aligned.m16n8k16.row.col.f32.f16.f16.f32 "
        "{%0,%1,%2,%3}, {%4,%5,%6,%7}, {%8,%9}, {%0,%1,%2,%3};"
        : "+f"(c[0]), "+f"(c[1]), "+f"(c[2]), "+f"(c[3])
        : "r"(a0), "r"(a1), "r"(a2), "r"(a3), "r"(b0), "r"(b1));
}

template <int BN, typename AT, bool SCALE>
__global__ void __launch_bounds__(256)
hgemm_kernel(const AT* __restrict__ A, const __half* __restrict__ Wt,
             __half* __restrict__ out, int M, int K) {
    constexpr int BM = 128, BK = 32;
    constexpr int SA = BK + 8;
    constexpr int SB = BK + 8;
    constexpr int WTN = BN / 4;
    constexpr int MB = 4;
    constexpr int NB = WTN / 8;

    __shared__ __half As[BM * SA];
    __shared__ __half Bs[BN * SB];

    const int tid  = threadIdx.x;
    const int lane = tid & 31;
    const int wid  = tid >> 5;
    const int wr   = wid >> 2;
    const int wc   = wid & 3;
    const int rowBlock = blockIdx.x * BM;

    float acc[MB][NB][4];
#pragma unroll
    for (int i = 0; i < MB; i++)
#pragma unroll
        for (int j = 0; j < NB; j++)
#pragma unroll
            for (int q = 0; q < 4; q++) acc[i][j][q] = 0.0f;

    const int lq = lane >> 2;
    const int lr = lane & 3;

    for (int kb = 0; kb < K; kb += BK) {
#pragma unroll
        for (int i = 0; i < 2; i++) {
            const int f  = tid + i * 256;
            const int r  = f >> 2;
            const int c0 = (f & 3) * 8;
            const int gr = rowBlock + r;
            uint4 v = make_uint4(0, 0, 0, 0);
            if (gr < M) {
                if constexpr (sizeof(AT) == 2) {
                    v = *reinterpret_cast<const uint4*>(
                        reinterpret_cast<const __half*>(A) + (size_t)gr * K + kb + c0);
                } else {
                    const float* ap = reinterpret_cast<const float*>(A) + (size_t)gr * K + kb + c0;
                    const float4 u0 = *reinterpret_cast<const float4*>(ap);
                    const float4 u1 = *reinterpret_cast<const float4*>(ap + 4);
                    *reinterpret_cast<__half2*>(&v.x) = __float22half2_rn(make_float2(u0.x, u0.y));
                    *reinterpret_cast<__half2*>(&v.y) = __float22half2_rn(make_float2(u0.z, u0.w));
                    *reinterpret_cast<__half2*>(&v.z) = __float22half2_rn(make_float2(u1.x, u1.y));
                    *reinterpret_cast<__half2*>(&v.w) = __float22half2_rn(make_float2(u1.z, u1.w));
                }
            }
            *reinterpret_cast<uint4*>(&As[r * SA + c0]) = v;
        }
#pragma unroll
        for (int i = 0; i < BN / 64; i++) {
            const int f  = tid + i * 256;
            const int n  = f >> 2;
            const int c0 = (f & 3) * 8;
            *reinterpret_cast<uint4*>(&Bs[n * SB + c0]) =
                *reinterpret_cast<const uint4*>(Wt + (size_t)n * K + kb + c0);
        }
        __syncthreads();

#pragma unroll
        for (int k16 = 0; k16 < BK / 16; k16++) {
            const int cb = k16 * 16 + 2 * lr;
            uint32_t af[MB][4];
#pragma unroll
            for (int mb = 0; mb < MB; mb++) {
                const int r = wr * 64 + mb * 16 + lq;
                af[mb][0] = *reinterpret_cast<const uint32_t*>(&As[r * SA + cb]);
                af[mb][1] = *reinterpret_cast<const uint32_t*>(&As[(r + 8) * SA + cb]);
                af[mb][2] = *reinterpret_cast<const uint32_t*>(&As[r * SA + cb + 8]);
                af[mb][3] = *reinterpret_cast<const uint32_t*>(&As[(r + 8) * SA + cb + 8]);
            }
            uint32_t bf[NB][2];
#pragma unroll
            for (int nb = 0; nb < NB; nb++) {
                const int n = wc * WTN + nb * 8 + lq;
                bf[nb][0] = *reinterpret_cast<const uint32_t*>(&Bs[n * SB + cb]);
                bf[nb][1] = *reinterpret_cast<const uint32_t*>(&Bs[n * SB + cb + 8]);
            }
#pragma unroll
            for (int mb = 0; mb < MB; mb++)
#pragma unroll
                for (int nb = 0; nb < NB; nb++)
                    mma_f16(acc[mb][nb], af[mb][0], af[mb][1], af[mb][2], af[mb][3],
                            bf[nb][0], bf[nb][1]);
        }
        __syncthreads();
    }

#pragma unroll
    for (int mb = 0; mb < MB; mb++) {
        const int r0 = rowBlock + wr * 64 + mb * 16 + lq;
        const int r1 = r0 + 8;
        float s0 = 1.f, s1 = 1.f;
        if (SCALE) {
            if (r0 < M) s0 = g_dinv[r0];
            if (r1 < M) s1 = g_dinv[r1];
        }
#pragma unroll
        for (int nb = 0; nb < NB; nb++) {
            const int c = wc * WTN + nb * 8 + lr * 2;
            if (r0 < M)
                *reinterpret_cast<__half2*>(out + (size_t)r0 * BN + c) =
                    __float22half2_rn(make_float2(acc[mb][nb][0] * s0, acc[mb][nb][1] * s0));
            if (r1 < M)
                *reinterpret_cast<__half2*>(out + (size_t)r1 * BN + c) =
                    __float22half2_rn(make_float2(acc[mb][nb][2] * s1, acc[mb][nb][3] * s1));
        }
    }
}

// ----------------------------- aggregation ----------------------------------
struct F8 { float v[8]; };

__device__ __forceinline__ F8 h8_to_f8(uint4 r) {
    F8 o;
    const float2 f0 = __half22float2(*reinterpret_cast<const __half2*>(&r.x));
    const float2 f1 = __half22float2(*reinterpret_cast<const __half2*>(&r.y));
    const float2 f2 = __half22float2(*reinterpret_cast<const __half2*>(&r.z));
    const float2 f3 = __half22float2(*reinterpret_cast<const __half2*>(&r.w));
    o.v[0] = f0.x; o.v[1] = f0.y; o.v[2] = f1.x; o.v[3] = f1.y;
    o.v[4] = f2.x; o.v[5] = f2.y; o.v[6] = f3.x; o.v[7] = f3.y;
    return o;
}

// Padded CSR: segment lengths multiples of 4, pads -> zero row N.
template <int C, int RELU, bool PRESCALED>
__global__ void agg_kernel(const __half* __restrict__ h, const float* __restrict__ b,
                           __half* __restrict__ out, int N) {
    constexpr int G = C / 8;
    const long long gt = (long long)blockIdx.x * blockDim.x + threadIdx.x;
    const int node = (int)(gt / G);
    const int lane = (int)(gt % G);
    if (node >= N) return;

    const int beg = g_rowptr[node];
    const int end = g_rowptr[node + 1];
    const size_t col = (size_t)lane * 8;
    const float di = g_dinv[node];

    const F8 self = h8_to_f8(*reinterpret_cast<const uint4*>(h + (size_t)node * C + col));
    float acc[8];
#pragma unroll
    for (int q = 0; q < 8; q++) acc[q] = PRESCALED ? self.v[q] : self.v[q] * di;

    for (int k = beg; k < end; k += 4) {
        const uint4 s4 = __ldg(reinterpret_cast<const uint4*>(&g_csr[k]));
        const int s0 = (int)s4.x, s1 = (int)s4.y, s2 = (int)s4.z, s3 = (int)s4.w;
        const F8 v0 = h8_to_f8(__ldg(reinterpret_cast<const uint4*>(h + (size_t)s0 * C + col)));
        const F8 v1 = h8_to_f8(__ldg(reinterpret_cast<const uint4*>(h + (size_t)s1 * C + col)));
        const F8 v2 = h8_to_f8(__ldg(reinterpret_cast<const uint4*>(h + (size_t)s2 * C + col)));
        const F8 v3 = h8_to_f8(__ldg(reinterpret_cast<const uint4*>(h + (size_t)s3 * C + col)));
        if (PRESCALED) {
#pragma unroll
            for (int q = 0; q < 8; q++)
                acc[q] += (v0.v[q] + v1.v[q]) + (v2.v[q] + v3.v[q]);
        } else {
            const float d0 = __ldg(&g_dinv[s0]);
            const float d1 = __ldg(&g_dinv[s1]);
            const float d2 = __ldg(&g_dinv[s2]);
            const float d3 = __ldg(&g_dinv[s3]);
#pragma unroll
            for (int q = 0; q < 8; q++) {
                acc[q] = fmaf(v0.v[q], d0, acc[q]);
                acc[q] = fmaf(v1.v[q], d1, acc[q]);
                acc[q] = fmaf(v2.v[q], d2, acc[q]);
                acc[q] = fmaf(v3.v[q], d3, acc[q]);
            }
        }
    }

    const float4 b0 = __ldg(reinterpret_cast<const float4*>(b + col));
    const float4 b1 = __ldg(reinterpret_cast<const float4*>(b + col + 4));
    const float bb[8] = {b0.x, b0.y, b0.z, b0.w, b1.x, b1.y, b1.z, b1.w};
    float r[8];
#pragma unroll
    for (int q = 0; q < 8; q++) {
        r[q] = fmaf(acc[q], di, bb[q]);
        if (RELU) r[q] = fmaxf(r[q], 0.f);
    }
    uint4 o;
    *reinterpret_cast<__half2*>(&o.x) = __float22half2_rn(make_float2(r[0], r[1]));
    *reinterpret_cast<__half2*>(&o.y) = __float22half2_rn(make_float2(r[2], r[3]));
    *reinterpret_cast<__half2*>(&o.z) = __float22half2_rn(make_float2(r[4], r[5]));
    *reinterpret_cast<__half2*>(&o.w) = __float22half2_rn(make_float2(r[6], r[7]));
    *reinterpret_cast<uint4*>(out + (size_t)node * C + col) = o;
}

// -------------------------------- edge MLP ----------------------------------
// 16 lanes per edge (2 edges/warp); each lane: 8B P loads, 1 float4 w load.
__global__ void edge_mlp_kernel(const int* __restrict__ src,
                                const int* __restrict__ dst,
                                const __half* __restrict__ P,     // [N,64] fp16
                                const float* __restrict__ b1,     // [64]
                                const float* __restrict__ w2,     // [64,2]
                                const float* __restrict__ b2,     // [2]
                                float* __restrict__ out, int E) {
    const long long gt = (long long)blockIdx.x * blockDim.x + threadIdx.x;
    const int edge = (int)(gt >> 4);
    const int lane = (int)(gt & 15);
    if (edge >= E) return;
    const int s = src[edge];
    const int d = dst[edge];
    const uint2 rs = __ldg(reinterpret_cast<const uint2*>(P + (size_t)s * 64 + lane * 4));
    const uint2 rd = __ldg(reinterpret_cast<const uint2*>(P + (size_t)d * 64 + lane * 4));
    const float2 ps0 = __half22float2(*reinterpret_cast<const __half2*>(&rs.x));
    const float2 ps1 = __half22float2(*reinterpret_cast<const __half2*>(&rs.y));
    const float2 pd0 = __half22float2(*reinterpret_cast<const __half2*>(&rd.x));
    const float2 pd1 = __half22float2(*reinterpret_cast<const __half2*>(&rd.y));
    const float4 bb = *reinterpret_cast<const float4*>(b1 + lane * 4);
    const float q0 = fmaxf(0.f, fmaf(ps0.x + pd0.x, 0.5f, bb.x));
    const float q1 = fmaxf(0.f, fmaf(ps0.y + pd0.y, 0.5f, bb.y));
    const float q2 = fmaxf(0.f, fmaf(ps1.x + pd1.x, 0.5f, bb.z));
    const float q3 = fmaxf(0.f, fmaf(ps1.y + pd1.y, 0.5f, bb.w));
    const float4 wA = *reinterpret_cast<const float4*>(w2 + lane * 8);
    const float4 wB = *reinterpret_cast<const float4*>(w2 + lane * 8 + 4);
    float y0 = q0 * wA.x + q1 * wA.z + q2 * wB.x + q3 * wB.z;
    float y1 = q0 * wA.y + q1 * wA.w + q2 * wB.y + q3 * wB.w;
#pragma unroll
    for (int o = 8; o > 0; o >>= 1) {
        y0 += __shfl_xor_sync(0xffffffffu, y0, o, 16);
        y1 += __shfl_xor_sync(0xffffffffu, y1, o, 16);
    }
    if (lane == 0) {
        float2 r;
        r.x = y0 + b2[0];
        r.y = y1 + b2[1];
        *reinterpret_cast<float2*>(out + (size_t)edge * 2) = r;
    }
}

// ---------------------------------------------------------------------------
extern "C" void kernel_launch(void* const* d_in, const int* in_sizes, int n_in,
                              void* d_out, int out_size) {
    const float* x   = (const float*)d_in[0];
    const int*   ei  = (const int*)d_in[1];   // int32
    const float* W0  = (const float*)d_in[2];
    const float* b0  = (const float*)d_in[3];
    const float* W1  = (const float*)d_in[4];
    const float* b1  = (const float*)d_in[5];
    const float* W2  = (const float*)d_in[6];
    const float* b2  = (const float*)d_in[7];
    const float* mw1 = (const float*)d_in[8];
    const float* mb1 = (const float*)d_in[9];
    const float* mw2 = (const float*)d_in[10];
    const float* mb2 = (const float*)d_in[11];
    float* out = (float*)d_out;

    const int N = in_sizes[0] / 128;
    const int E = in_sizes[1] / 2;
    const int* src = ei;
    const int* dst = ei + E;

    __half *pH, *pC16, *pW0t, *pW1t, *pW2t;
    float  *pb2p;
    cudaGetSymbolAddress((void**)&pH,   g_H);
    cudaGetSymbolAddress((void**)&pC16, g_C16);
    cudaGetSymbolAddress((void**)&pW0t, g_W0t);
    cudaGetSymbolAddress((void**)&pW1t, g_W1t);
    cudaGetSymbolAddress((void**)&pW2t, g_W2t);
    cudaGetSymbolAddress((void**)&pb2p, g_b2p);

    const int T = 256;
    const int nScanBlocks = (N + SCAN_B - 1) / SCAN_B;

    static cudaStream_t s_side = (cudaStream_t)(-1);
    static cudaEvent_t  ev_fork = nullptr, ev_join = nullptr;
    if (s_side == (cudaStream_t)(-1)) {
        cudaStream_t tmp;
        if (cudaStreamCreateWithFlags(&tmp, cudaStreamNonBlocking) == cudaSuccess &&
            cudaEventCreateWithFlags(&ev_fork, cudaEventDisableTiming) == cudaSuccess &&
            cudaEventCreateWithFlags(&ev_join, cudaEventDisableTiming) == cudaSuccess) {
            s_side = tmp;
        } else {
            s_side = nullptr;
        }
    }
    const bool overlap = (s_side != nullptr);
    cudaStream_t sc = overlap ? s_side : (cudaStream_t)0;

    if (overlap) {
        cudaEventRecord(ev_fork, 0);
        cudaStreamWaitEvent(s_side, ev_fork, 0);
    }

    const int gM = (N + 127) / 128;
    const int agg128 = (int)(((long long)N * 16 + T - 1) / T);
    const int agg64  = (int)(((long long)N * 8 + T - 1) / T);

    // main: GEMM0 (fp32 A, converts inline) ; side: CSR + weight prep
    prep_wt_kernel<<<(128 * 128 + T - 1) / T, T>>>(W0, pW0t, 128, 128);
    deg_zero_kernel<<<(N + T - 1) / T, T, 0, sc>>>(N);
    deg_count_kernel<<<(E + T - 1) / T, T, 0, sc>>>(dst, E);
    partial_scan_kernel<<<nScanBlocks, SCAN_B, 0, sc>>>(N);
    hgemm_kernel<128, float, false><<<gM, T>>>(x, pW0t, pH, N, 128);
    bsum_scan_kernel<<<1, 128, 0, sc>>>(nScanBlocks);
    add_offsets_kernel<<<(N + T) / T, T, 0, sc>>>(N);
    pad_fill_kernel<<<(N + T - 1) / T, T, 0, sc>>>(N);
    fill_kernel<<<(E + T - 1) / T, T, 0, sc>>>(src, dst, E);
    prep_wt_kernel<<<(128 * 128 + T - 1) / T, T, 0, sc>>>(W1, pW1t, 128, 128);
    fold_w2t_kernel<<<64, 128, 0, sc>>>(W2, mw1);
    fold_b2_kernel<<<1, 64, 0, sc>>>(b2, mw1);

    if (overlap) {
        cudaEventRecord(ev_join, s_side);
        cudaStreamWaitEvent(0, ev_join, 0);
    }

    // ---- GCN layer 0 agg (dinv gathered; pads: dinv[N]=0) ----
    agg_kernel<128, 1, false><<<agg128, T>>>(pH, b0, pC16, N);

    // ---- GCN layer 1 (prescaled -> pure-add agg; zero row N*128 intact) ----
    hgemm_kernel<128, __half, true><<<gM, T>>>(pC16, pW1t, pH, N, 128);
    agg_kernel<128, 1, true><<<agg128, T>>>(pH, b1, pC16, N);

    // ---- GCN layer 2 fused with mlp_w1 (prescaled, C=64) ----
    hgemm_kernel<64, __half, true><<<gM, T>>>(pC16, pW2t, pH, N, 128);
    zero_row_kernel<<<1, 64>>>(pH, N, 64);   // C=64 sentinel row overlaps old data
    agg_kernel<64, 0, true><<<agg64, T>>>(pH, pb2p, pC16, N);   // pC16 = P

    // ---- edge head ----
    edge_mlp_kernel<<<(int)(((long long)E * 16 + T - 1) / T), T>>>(src, dst, pC16, mb1, mw2, mb2, out, E);
}

// round 17
// speedup vs baseline: 1.0520x; 1.0327x over previous
#include <cuda_runtime.h>
#include <cuda_fp16.h>
#include <math.h>
#include <stdint.h>

// ---------------------------------------------------------------------------
// 3-layer GCN (N=100000, E=1600000, C: 128->128->128->64) + edge MLP.
// GEMMs: fp16 mma.sync.m16n8k16; weights pre-transposed fp16; GEMM0 converts
// fp32 A inline; GEMM1/2 prescale rows by dinv. Aggregation: plain CSR,
// x4-unrolled 16B/lane row gathers (R12 champion config).
// bsum_scan + add_offsets fused with BLOCK-UNIFORM barriers (R16 had a
// divergent __syncthreads -> UB -> corrupted rowptr -> address trap).
// Layer2 folded with mlp_w1. CSR + weight prep on side stream.
// edge_index is int32 (JAX x64 disabled).
// ---------------------------------------------------------------------------

#define MAXN 100000
#define MAXE 2000000
#define SCAN_B 1024
#define MAXBLK 128

__device__ __half g_H[(size_t)MAXN * 128];   // fp16 GEMM-output gather table
__device__ __half g_C16[(size_t)MAXN * 128]; // fp16 activations (h / P)
__device__ float  g_dinv[MAXN];
__device__ int    g_deg[MAXN];
__device__ int    g_rowptr[MAXN + 1];
__device__ int    g_fill[MAXN];
__device__ int    g_csr[MAXE];
__device__ int    g_bsum[MAXBLK];
__device__ __half g_W0t[128 * 128];
__device__ __half g_W1t[128 * 128];
__device__ __half g_W2t[64 * 128];
__device__ float  g_b2p[64];

// ------------------------------ degree / CSR --------------------------------
__global__ void deg_zero_kernel(int N) {
    int i = blockIdx.x * blockDim.x + threadIdx.x;
    if (i < N) { g_deg[i] = 0; g_fill[i] = 0; }
}

__global__ void deg_count_kernel(const int* __restrict__ dst, int E) {
    int i = blockIdx.x * blockDim.x + threadIdx.x;
    if (i < E) atomicAdd(&g_deg[dst[i]], 1);
}

__global__ void partial_scan_kernel(int N) {
    __shared__ int wsum[32];
    __shared__ int wpre[32];
    const int lane = threadIdx.x & 31;
    const int wid  = threadIdx.x >> 5;
    const int i = blockIdx.x * SCAN_B + threadIdx.x;
    const int v = (i < N) ? g_deg[i] : 0;
    if (i < N) g_dinv[i] = rsqrtf((float)(v + 1));  // +1 self loop

    int inc = v;
#pragma unroll
    for (int o = 1; o < 32; o <<= 1) {
        int t = __shfl_up_sync(0xffffffffu, inc, o);
        if (lane >= o) inc += t;
    }
    if (lane == 31) wsum[wid] = inc;
    __syncthreads();
    if (wid == 0) {
        int s = wsum[lane];
        int sinc = s;
#pragma unroll
        for (int o = 1; o < 32; o <<= 1) {
            int t = __shfl_up_sync(0xffffffffu, sinc, o);
            if (lane >= o) sinc += t;
        }
        wpre[lane] = sinc - s;
        if (lane == 31) wsum[0] = sinc;
    }
    __syncthreads();
    if (i < N) g_rowptr[i] = wpre[wid] + inc - v;   // local exclusive
    if (threadIdx.x == 0) g_bsum[blockIdx.x] = wsum[0];
}

// Fused bsum scan + offset apply. ALL barriers are block-uniform: every
// thread computes its (possibly zero) scan contribution; warps beyond the
// first four scan zeros harmlessly.
__global__ void add_offsets_kernel(int N, int E, int nb) {
    __shared__ int off[MAXBLK];
    __shared__ int wtot[8];
    const int lane = threadIdx.x & 31;
    const int w    = threadIdx.x >> 5;           // 0..7 (blockDim = 256)
    const int v = (threadIdx.x < nb) ? g_bsum[threadIdx.x] : 0;
    int inc = v;
#pragma unroll
    for (int o = 1; o < 32; o <<= 1) {
        int t = __shfl_up_sync(0xffffffffu, inc, o);
        if (lane >= o) inc += t;
    }
    if (lane == 31) wtot[w] = inc;
    __syncthreads();
    if (threadIdx.x < MAXBLK) {
        int pre = 0;
#pragma unroll
        for (int ww = 0; ww < 4; ww++) if (ww < w) pre += wtot[ww];
        off[threadIdx.x] = pre + inc - v;        // exclusive prefix
    }
    __syncthreads();
    const int i = blockIdx.x * blockDim.x + threadIdx.x;
    if (i < N) g_rowptr[i] += off[i >> 10];
    if (i == N) g_rowptr[N] = E;
}

__global__ void fill_kernel(const int* __restrict__ src, const int* __restrict__ dst, int E) {
    int e = blockIdx.x * blockDim.x + threadIdx.x;
    if (e < E) {
        const int d = dst[e];
        const int pos = g_rowptr[d] + atomicAdd(&g_fill[d], 1);
        g_csr[pos] = src[e];
    }
}

// ---------------------------- weight preparation -----------------------------
__global__ void prep_wt_kernel(const float* __restrict__ W, __half* __restrict__ Wt,
                               int K, int Ncols) {
    const int idx = blockIdx.x * blockDim.x + threadIdx.x;
    if (idx < K * Ncols) {
        const int k = idx / Ncols;
        const int n = idx % Ncols;
        Wt[n * K + k] = __float2half_rn(W[idx]);
    }
}

__global__ void fold_w2t_kernel(const float* __restrict__ W2, const float* __restrict__ mw1) {
    const int j = blockIdx.x;     // 0..63
    const int i = threadIdx.x;    // 0..127
    float s = 0.f;
#pragma unroll 8
    for (int k = 0; k < 64; k++)
        s = fmaf(W2[i * 64 + k], mw1[k * 64 + j], s);
    g_W2t[j * 128 + i] = __float2half_rn(s);
}

__global__ void fold_b2_kernel(const float* __restrict__ b2, const float* __restrict__ mw1) {
    const int j = threadIdx.x;
    float s = 0.f;
#pragma unroll 8
    for (int k = 0; k < 64; k++)
        s = fmaf(b2[k], mw1[k * 64 + j], s);
    g_b2p[j] = s;
}

// ------------------------------ fp16 GEMM -----------------------------------
__device__ __forceinline__ void mma_f16(float* c, uint32_t a0, uint32_t a1,
                                        uint32_t a2, uint32_t a3,
                                        uint32_t b0, uint32_t b1) {
    asm volatile(
        "mma.sync.aligned.m16n8k16.row.col.f32.f16.f16.f32 "
        "{%0,%1,%2,%3}, {%4,%5,%6,%7}, {%8,%9}, {%0,%1,%2,%3};"
        : "+f"(c[0]), "+f"(c[1]), "+f"(c[2]), "+f"(c[3])
        : "r"(a0), "r"(a1), "r"(a2), "r"(a3), "r"(b0), "r"(b1));
}

template <int BN, typename AT, bool SCALE>
__global__ void __launch_bounds__(256)
hgemm_kernel(const AT* __restrict__ A, const __half* __restrict__ Wt,
             __half* __restrict__ out, int M, int K) {
    constexpr int BM = 128, BK = 32;
    constexpr int SA = BK + 8;
    constexpr int SB = BK + 8;
    constexpr int WTN = BN / 4;
    constexpr int MB = 4;
    constexpr int NB = WTN / 8;

    __shared__ __half As[BM * SA];
    __shared__ __half Bs[BN * SB];

    const int tid  = threadIdx.x;
    const int lane = tid & 31;
    const int wid  = tid >> 5;
    const int wr   = wid >> 2;
    const int wc   = wid & 3;
    const int rowBlock = blockIdx.x * BM;

    float acc[MB][NB][4];
#pragma unroll
    for (int i = 0; i < MB; i++)
#pragma unroll
        for (int j = 0; j < NB; j++)
#pragma unroll
            for (int q = 0; q < 4; q++) acc[i][j][q] = 0.0f;

    const int lq = lane >> 2;
    const int lr = lane & 3;

    for (int kb = 0; kb < K; kb += BK) {
#pragma unroll
        for (int i = 0; i < 2; i++) {
            const int f  = tid + i * 256;
            const int r  = f >> 2;
            const int c0 = (f & 3) * 8;
            const int gr = rowBlock + r;
            uint4 v = make_uint4(0, 0, 0, 0);
            if (gr < M) {
                if constexpr (sizeof(AT) == 2) {
                    v = *reinterpret_cast<const uint4*>(
                        reinterpret_cast<const __half*>(A) + (size_t)gr * K + kb + c0);
                } else {
                    const float* ap = reinterpret_cast<const float*>(A) + (size_t)gr * K + kb + c0;
                    const float4 u0 = *reinterpret_cast<const float4*>(ap);
                    const float4 u1 = *reinterpret_cast<const float4*>(ap + 4);
                    *reinterpret_cast<__half2*>(&v.x) = __float22half2_rn(make_float2(u0.x, u0.y));
                    *reinterpret_cast<__half2*>(&v.y) = __float22half2_rn(make_float2(u0.z, u0.w));
                    *reinterpret_cast<__half2*>(&v.z) = __float22half2_rn(make_float2(u1.x, u1.y));
                    *reinterpret_cast<__half2*>(&v.w) = __float22half2_rn(make_float2(u1.z, u1.w));
                }
            }
            *reinterpret_cast<uint4*>(&As[r * SA + c0]) = v;
        }
#pragma unroll
        for (int i = 0; i < BN / 64; i++) {
            const int f  = tid + i * 256;
            const int n  = f >> 2;
            const int c0 = (f & 3) * 8;
            *reinterpret_cast<uint4*>(&Bs[n * SB + c0]) =
                *reinterpret_cast<const uint4*>(Wt + (size_t)n * K + kb + c0);
        }
        __syncthreads();

#pragma unroll
        for (int k16 = 0; k16 < BK / 16; k16++) {
            const int cb = k16 * 16 + 2 * lr;
            uint32_t af[MB][4];
#pragma unroll
            for (int mb = 0; mb < MB; mb++) {
                const int r = wr * 64 + mb * 16 + lq;
                af[mb][0] = *reinterpret_cast<const uint32_t*>(&As[r * SA + cb]);
                af[mb][1] = *reinterpret_cast<const uint32_t*>(&As[(r + 8) * SA + cb]);
                af[mb][2] = *reinterpret_cast<const uint32_t*>(&As[r * SA + cb + 8]);
                af[mb][3] = *reinterpret_cast<const uint32_t*>(&As[(r + 8) * SA + cb + 8]);
            }
            uint32_t bf[NB][2];
#pragma unroll
            for (int nb = 0; nb < NB; nb++) {
                const int n = wc * WTN + nb * 8 + lq;
                bf[nb][0] = *reinterpret_cast<const uint32_t*>(&Bs[n * SB + cb]);
                bf[nb][1] = *reinterpret_cast<const uint32_t*>(&Bs[n * SB + cb + 8]);
            }
#pragma unroll
            for (int mb = 0; mb < MB; mb++)
#pragma unroll
                for (int nb = 0; nb < NB; nb++)
                    mma_f16(acc[mb][nb], af[mb][0], af[mb][1], af[mb][2], af[mb][3],
                            bf[nb][0], bf[nb][1]);
        }
        __syncthreads();
    }

#pragma unroll
    for (int mb = 0; mb < MB; mb++) {
        const int r0 = rowBlock + wr * 64 + mb * 16 + lq;
        const int r1 = r0 + 8;
        float s0 = 1.f, s1 = 1.f;
        if (SCALE) {
            if (r0 < M) s0 = g_dinv[r0];
            if (r1 < M) s1 = g_dinv[r1];
        }
#pragma unroll
        for (int nb = 0; nb < NB; nb++) {
            const int c = wc * WTN + nb * 8 + lr * 2;
            if (r0 < M)
                *reinterpret_cast<__half2*>(out + (size_t)r0 * BN + c) =
                    __float22half2_rn(make_float2(acc[mb][nb][0] * s0, acc[mb][nb][1] * s0));
            if (r1 < M)
                *reinterpret_cast<__half2*>(out + (size_t)r1 * BN + c) =
                    __float22half2_rn(make_float2(acc[mb][nb][2] * s1, acc[mb][nb][3] * s1));
        }
    }
}

// ----------------------------- aggregation ----------------------------------
struct F8 { float v[8]; };

__device__ __forceinline__ F8 h8_to_f8(uint4 r) {
    F8 o;
    const float2 f0 = __half22float2(*reinterpret_cast<const __half2*>(&r.x));
    const float2 f1 = __half22float2(*reinterpret_cast<const __half2*>(&r.y));
    const float2 f2 = __half22float2(*reinterpret_cast<const __half2*>(&r.z));
    const float2 f3 = __half22float2(*reinterpret_cast<const __half2*>(&r.w));
    o.v[0] = f0.x; o.v[1] = f0.y; o.v[2] = f1.x; o.v[3] = f1.y;
    o.v[4] = f2.x; o.v[5] = f2.y; o.v[6] = f3.x; o.v[7] = f3.y;
    return o;
}

// PRESCALED: h rows already carry dinv_src -> acc = h_i + sum h_j (pure adds).
// else: acc = dinv_i*h_i + sum dinv_j*h_j. Output: maybe_relu(dinv_i*acc + b).
// 16B (8 halves) per lane; C/8 lanes per node; x4-unrolled prefetch + tail.
template <int C, int RELU, bool PRESCALED>
__global__ void agg_kernel(const __half* __restrict__ h, const float* __restrict__ b,
                           __half* __restrict__ out, int N) {
    constexpr int G = C / 8;
    const long long gt = (long long)blockIdx.x * blockDim.x + threadIdx.x;
    const int node = (int)(gt / G);
    const int lane = (int)(gt % G);
    if (node >= N) return;

    const int beg = g_rowptr[node];
    const int end = g_rowptr[node + 1];
    const size_t col = (size_t)lane * 8;
    const float di = g_dinv[node];

    const F8 self = h8_to_f8(*reinterpret_cast<const uint4*>(h + (size_t)node * C + col));
    float acc[8];
#pragma unroll
    for (int q = 0; q < 8; q++) acc[q] = PRESCALED ? self.v[q] : self.v[q] * di;

    int k = beg;
    for (; k + 4 <= end; k += 4) {
        const int s0 = __ldg(&g_csr[k]);
        const int s1 = __ldg(&g_csr[k + 1]);
        const int s2 = __ldg(&g_csr[k + 2]);
        const int s3 = __ldg(&g_csr[k + 3]);
        const F8 v0 = h8_to_f8(__ldg(reinterpret_cast<const uint4*>(h + (size_t)s0 * C + col)));
        const F8 v1 = h8_to_f8(__ldg(reinterpret_cast<const uint4*>(h + (size_t)s1 * C + col)));
        const F8 v2 = h8_to_f8(__ldg(reinterpret_cast<const uint4*>(h + (size_t)s2 * C + col)));
        const F8 v3 = h8_to_f8(__ldg(reinterpret_cast<const uint4*>(h + (size_t)s3 * C + col)));
        if (PRESCALED) {
#pragma unroll
            for (int q = 0; q < 8; q++)
                acc[q] += (v0.v[q] + v1.v[q]) + (v2.v[q] + v3.v[q]);
        } else {
            const float d0 = __ldg(&g_dinv[s0]);
            const float d1 = __ldg(&g_dinv[s1]);
            const float d2 = __ldg(&g_dinv[s2]);
            const float d3 = __ldg(&g_dinv[s3]);
#pragma unroll
            for (int q = 0; q < 8; q++) {
                acc[q] = fmaf(v0.v[q], d0, acc[q]);
                acc[q] = fmaf(v1.v[q], d1, acc[q]);
                acc[q] = fmaf(v2.v[q], d2, acc[q]);
                acc[q] = fmaf(v3.v[q], d3, acc[q]);
            }
        }
    }
    for (; k < end; k++) {
        const int s = __ldg(&g_csr[k]);
        const F8 v = h8_to_f8(__ldg(reinterpret_cast<const uint4*>(h + (size_t)s * C + col)));
        if (PRESCALED) {
#pragma unroll
            for (int q = 0; q < 8; q++) acc[q] += v.v[q];
        } else {
            const float ds = __ldg(&g_dinv[s]);
#pragma unroll
            for (int q = 0; q < 8; q++) acc[q] = fmaf(v.v[q], ds, acc[q]);
        }
    }

    const float4 b0 = __ldg(reinterpret_cast<const float4*>(b + col));
    const float4 b1 = __ldg(reinterpret_cast<const float4*>(b + col + 4));
    const float bb[8] = {b0.x, b0.y, b0.z, b0.w, b1.x, b1.y, b1.z, b1.w};
    float r[8];
#pragma unroll
    for (int q = 0; q < 8; q++) {
        r[q] = fmaf(acc[q], di, bb[q]);
        if (RELU) r[q] = fmaxf(r[q], 0.f);
    }
    uint4 o;
    *reinterpret_cast<__half2*>(&o.x) = __float22half2_rn(make_float2(r[0], r[1]));
    *reinterpret_cast<__half2*>(&o.y) = __float22half2_rn(make_float2(r[2], r[3]));
    *reinterpret_cast<__half2*>(&o.z) = __float22half2_rn(make_float2(r[4], r[5]));
    *reinterpret_cast<__half2*>(&o.w) = __float22half2_rn(make_float2(r[6], r[7]));
    *reinterpret_cast<uint4*>(out + (size_t)node * C + col) = o;
}

// -------------------------------- edge MLP ----------------------------------
// 16 lanes per edge (2 edges/warp); each lane: 8B P loads, 1 float4 w load.
__global__ void edge_mlp_kernel(const int* __restrict__ src,
                                const int* __restrict__ dst,
                                const __half* __restrict__ P,     // [N,64] fp16
                                const float* __restrict__ b1,     // [64]
                                const float* __restrict__ w2,     // [64,2]
                                const float* __restrict__ b2,     // [2]
                                float* __restrict__ out, int E) {
    const long long gt = (long long)blockIdx.x * blockDim.x + threadIdx.x;
    const int edge = (int)(gt >> 4);
    const int lane = (int)(gt & 15);
    if (edge >= E) return;
    const int s = src[edge];
    const int d = dst[edge];
    const uint2 rs = __ldg(reinterpret_cast<const uint2*>(P + (size_t)s * 64 + lane * 4));
    const uint2 rd = __ldg(reinterpret_cast<const uint2*>(P + (size_t)d * 64 + lane * 4));
    const float2 ps0 = __half22float2(*reinterpret_cast<const __half2*>(&rs.x));
    const float2 ps1 = __half22float2(*reinterpret_cast<const __half2*>(&rs.y));
    const float2 pd0 = __half22float2(*reinterpret_cast<const __half2*>(&rd.x));
    const float2 pd1 = __half22float2(*reinterpret_cast<const __half2*>(&rd.y));
    const float4 bb = *reinterpret_cast<const float4*>(b1 + lane * 4);
    const float q0 = fmaxf(0.f, fmaf(ps0.x + pd0.x, 0.5f, bb.x));
    const float q1 = fmaxf(0.f, fmaf(ps0.y + pd0.y, 0.5f, bb.y));
    const float q2 = fmaxf(0.f, fmaf(ps1.x + pd1.x, 0.5f, bb.z));
    const float q3 = fmaxf(0.f, fmaf(ps1.y + pd1.y, 0.5f, bb.w));
    const float4 wA = *reinterpret_cast<const float4*>(w2 + lane * 8);
    const float4 wB = *reinterpret_cast<const float4*>(w2 + lane * 8 + 4);
    float y0 = q0 * wA.x + q1 * wA.z + q2 * wB.x + q3 * wB.z;
    float y1 = q0 * wA.y + q1 * wA.w + q2 * wB.y + q3 * wB.w;
#pragma unroll
    for (int o = 8; o > 0; o >>= 1) {
        y0 += __shfl_xor_sync(0xffffffffu, y0, o, 16);
        y1 += __shfl_xor_sync(0xffffffffu, y1, o, 16);
    }
    if (lane == 0) {
        float2 r;
        r.x = y0 + b2[0];
        r.y = y1 + b2[1];
        *reinterpret_cast<float2*>(out + (size_t)edge * 2) = r;
    }
}

// ---------------------------------------------------------------------------
extern "C" void kernel_launch(void* const* d_in, const int* in_sizes, int n_in,
                              void* d_out, int out_size) {
    const float* x   = (const float*)d_in[0];
    const int*   ei  = (const int*)d_in[1];   // int32
    const float* W0  = (const float*)d_in[2];
    const float* b0  = (const float*)d_in[3];
    const float* W1  = (const float*)d_in[4];
    const float* b1  = (const float*)d_in[5];
    const float* W2  = (const float*)d_in[6];
    const float* b2  = (const float*)d_in[7];
    const float* mw1 = (const float*)d_in[8];
    const float* mb1 = (const float*)d_in[9];
    const float* mw2 = (const float*)d_in[10];
    const float* mb2 = (const float*)d_in[11];
    float* out = (float*)d_out;

    const int N = in_sizes[0] / 128;
    const int E = in_sizes[1] / 2;
    const int* src = ei;
    const int* dst = ei + E;

    __half *pH, *pC16, *pW0t, *pW1t, *pW2t;
    float  *pb2p;
    cudaGetSymbolAddress((void**)&pH,   g_H);
    cudaGetSymbolAddress((void**)&pC16, g_C16);
    cudaGetSymbolAddress((void**)&pW0t, g_W0t);
    cudaGetSymbolAddress((void**)&pW1t, g_W1t);
    cudaGetSymbolAddress((void**)&pW2t, g_W2t);
    cudaGetSymbolAddress((void**)&pb2p, g_b2p);

    const int T = 256;
    const int nScanBlocks = (N + SCAN_B - 1) / SCAN_B;

    static cudaStream_t s_side = (cudaStream_t)(-1);
    static cudaEvent_t  ev_fork = nullptr, ev_join = nullptr;
    if (s_side == (cudaStream_t)(-1)) {
        cudaStream_t tmp;
        if (cudaStreamCreateWithFlags(&tmp, cudaStreamNonBlocking) == cudaSuccess &&
            cudaEventCreateWithFlags(&ev_fork, cudaEventDisableTiming) == cudaSuccess &&
            cudaEventCreateWithFlags(&ev_join, cudaEventDisableTiming) == cudaSuccess) {
            s_side = tmp;
        } else {
            s_side = nullptr;
        }
    }
    const bool overlap = (s_side != nullptr);
    cudaStream_t sc = overlap ? s_side : (cudaStream_t)0;

    if (overlap) {
        cudaEventRecord(ev_fork, 0);
        cudaStreamWaitEvent(s_side, ev_fork, 0);
    }

    const int gM = (N + 127) / 128;
    const int agg128 = (int)(((long long)N * 16 + T - 1) / T);
    const int agg64  = (int)(((long long)N * 8 + T - 1) / T);

    // main: GEMM0 (fp32 A, converts inline) ; side: CSR + weight prep
    prep_wt_kernel<<<(128 * 128 + T - 1) / T, T>>>(W0, pW0t, 128, 128);
    deg_zero_kernel<<<(N + T - 1) / T, T, 0, sc>>>(N);
    deg_count_kernel<<<(E + T - 1) / T, T, 0, sc>>>(dst, E);
    partial_scan_kernel<<<nScanBlocks, SCAN_B, 0, sc>>>(N);
    hgemm_kernel<128, float, false><<<gM, T>>>(x, pW0t, pH, N, 128);
    add_offsets_kernel<<<(N + T) / T, T, 0, sc>>>(N, E, nScanBlocks);
    fill_kernel<<<(E + T - 1) / T, T, 0, sc>>>(src, dst, E);
    prep_wt_kernel<<<(128 * 128 + T - 1) / T, T, 0, sc>>>(W1, pW1t, 128, 128);
    fold_w2t_kernel<<<64, 128, 0, sc>>>(W2, mw1);
    fold_b2_kernel<<<1, 64, 0, sc>>>(b2, mw1);

    if (overlap) {
        cudaEventRecord(ev_join, s_side);
        cudaStreamWaitEvent(0, ev_join, 0);
    }

    // ---- GCN layer 0 agg (H unscaled -> dinv gathered per edge) ----
    agg_kernel<128, 1, false><<<agg128, T>>>(pH, b0, pC16, N);

    // ---- GCN layer 1 (GEMM prescales by dinv -> pure-add agg) ----
    hgemm_kernel<128, __half, true><<<gM, T>>>(pC16, pW1t, pH, N, 128);
    agg_kernel<128, 1, true><<<agg128, T>>>(pH, b1, pC16, N);

    // ---- GCN layer 2 fused with mlp_w1 (prescaled) ----
    hgemm_kernel<64, __half, true><<<gM, T>>>(pC16, pW2t, pH, N, 128);
    agg_kernel<64, 0, true><<<agg64, T>>>(pH, pb2p, pC16, N);   // pC16 = P

    // ---- edge head ----
    edge_mlp_kernel<<<(int)(((long long)E * 16 + T - 1) / T), T>>>(src, dst, pC16, mb1, mw2, mb2, out, E);
}